// round 6
// baseline (speedup 1.0000x reference)
#include <cuda_runtime.h>
#include <cstdint>

typedef unsigned long long u64;
typedef unsigned int u32;

// ---------------- problem constants ----------------
#define NA 9
#define HWPIX 65536
#define TOT 589824
#define PRE 6000
#define POST 300
#define NMS_T 0.7f
#define NWORDS 94
#define WPITCH 96
#define CAPBIG 16384
#define SORTN 8192
#define NBINS 65536
#define NTHR 1024

// ---------------- scratch ----------------
__device__ u32 g_barcnt;            // monotonic across replays (relative targets)
__device__ u32 g_obs[TOT];          // item-major: [a][pix]
__device__ u32 g_hist[NBINS];
__device__ u32 g_hist2[NBINS];
__device__ int g_T1;
__device__ u32 g_above;
__device__ u64 g_thr64;
__device__ int g_candcnt;
__device__ int g_cnt2;
__device__ u64 g_cand[CAPBIG];
__device__ u64 g_sortbuf[SORTN];
__device__ float4 g_boxes[PRE];
__device__ float  g_area[PRE];
__device__ u64 g_supp[WPITCH];
__device__ u64 g_mask[(size_t)PRE * WPITCH];

// ---------------- software grid barrier (monotonic counter, no reset) ----------------
__device__ __forceinline__ void gbar()
{
    __syncthreads();
    if (threadIdx.x == 0) {
        __threadfence();
        u32 nb = gridDim.x;
        u32 my = atomicAdd(&g_barcnt, 1u) + 1u;
        u32 rem = my % nb;
        u32 tgt = rem ? my + (nb - rem) : my;
        while ((int)(atomicAdd(&g_barcnt, 0u) - tgt) < 0) __nanosleep(64);
    }
    __syncthreads();
}

// ---------------- box decode (explicit RN: match XLA no-fma) ----------------
__device__ __forceinline__ float4 decode_box(int pix, int a,
                                             const float* __restrict__ del,
                                             const float4* __restrict__ anc,
                                             float imW1, float imH1, float ms,
                                             bool& valid)
{
    float sx = __fmul_rn((float)(pix & 255), 16.0f);
    float sy = __fmul_rn((float)(pix >> 8), 16.0f);
    float4 A = anc[a];
    float ax1 = __fadd_rn(A.x, sx);
    float ay1 = __fadd_rn(A.y, sy);
    float ax2 = __fadd_rn(A.z, sx);
    float ay2 = __fadd_rn(A.w, sy);
    float aw  = __fadd_rn(__fsub_rn(ax2, ax1), 1.0f);
    float ah  = __fadd_rn(__fsub_rn(ay2, ay1), 1.0f);
    float acx = __fadd_rn(ax1, __fmul_rn(0.5f, aw));
    float acy = __fadd_rn(ay1, __fmul_rn(0.5f, ah));

    int base = (4 * a) * HWPIX + pix;
    float dx = del[base];
    float dy = del[base + HWPIX];
    float dw = del[base + 2 * HWPIX];
    float dh = del[base + 3 * HWPIX];
    dw = fminf(fmaxf(dw, -10.0f), 10.0f);
    dh = fminf(fmaxf(dh, -10.0f), 10.0f);

    float pcx = __fadd_rn(__fmul_rn(dx, aw), acx);
    float pcy = __fadd_rn(__fmul_rn(dy, ah), acy);
    float pw  = __fmul_rn(expf(dw), aw);
    float ph  = __fmul_rn(expf(dh), ah);

    float hx = __fmul_rn(0.5f, pw);
    float hy = __fmul_rn(0.5f, ph);
    float x1 = fminf(fmaxf(__fsub_rn(pcx, hx), 0.0f), imW1);
    float y1 = fminf(fmaxf(__fsub_rn(pcy, hy), 0.0f), imH1);
    float x2 = fminf(fmaxf(__fsub_rn(__fadd_rn(pcx, hx), 1.0f), 0.0f), imW1);
    float y2 = fminf(fmaxf(__fsub_rn(__fadd_rn(pcy, hy), 1.0f), 0.0f), imH1);

    valid = (__fadd_rn(__fsub_rn(x2, x1), 1.0f) >= ms) &&
            (__fadd_rn(__fsub_rn(y2, y1), 1.0f) >= ms);
    return make_float4(x1, y1, x2, y2);
}

// ---------------- parallel threshold search (block 0 only) ----------------
__device__ __forceinline__ void threshold_search(const u32* __restrict__ hist,
                                                 int target, int* outBin, u32* outAbove)
{
    __shared__ u32 co[1024];
    __shared__ u32 fs[64];
    __shared__ int c_blk;
    __shared__ u32 above_c;
    int t = threadIdx.x;

    u32 s = 0;
#pragma unroll 8
    for (int b = 0; b < 64; ++b) s += hist[t * 64 + b];
    u32 cur = s;
    co[t] = cur;
    __syncthreads();
    for (int off = 1; off < 1024; off <<= 1) {
        u32 oth = (t + off < 1024) ? co[t + off] : 0u;
        __syncthreads();
        cur += oth;
        co[t] = cur;
        __syncthreads();
    }
    if (t == 0) c_blk = -1;
    __syncthreads();
    u32 nxt = (t < 1023) ? co[t + 1] : 0u;
    if (cur >= (u32)target && nxt < (u32)target) { c_blk = t; above_c = nxt; }
    __syncthreads();

    int c = c_blk;
    if (c < 0) { if (t == 0) { *outBin = 0; *outAbove = 0u; } return; }
    if (t < 64) fs[t] = hist[c * 64 + t];
    __syncthreads();
    if (t == 0) {
        u32 acc = above_c;
        int b;
        for (b = 63; b >= 0; --b) {
            acc += fs[b];
            if (acc >= (u32)target) break;
        }
        if (b < 0) b = 0;
        *outBin = c * 64 + b;
        *outAbove = acc - fs[b];
    }
}

// ---------------- THE fused persistent kernel ----------------
__global__ void __launch_bounds__(NTHR, 1)
fused_proposal(const float* __restrict__ probs,
               const float* __restrict__ del,
               const float* __restrict__ img,
               const float* __restrict__ anchors,
               float* __restrict__ out)
{
    extern __shared__ u64 sk[];                     // 64KB dynamic (sort)
    __shared__ float4 cb[64];
    __shared__ float  ca[64];
    __shared__ int   sh_bin;
    __shared__ u32   sh_above;

    const int tid  = threadIdx.x;
    const int gtid = blockIdx.x * NTHR + tid;
    const int gs   = gridDim.x * NTHR;
    const int nb   = gridDim.x;
    const int lane = tid & 31;

    // ---- P0: zero scratch ----
    for (int i = gtid; i < NBINS; i += gs) { g_hist[i] = 0u; g_hist2[i] = 0u; }
    for (int i = gtid; i < SORTN; i += gs) g_sortbuf[i] = 0ull;
    for (int i = gtid; i < WPITCH; i += gs) g_supp[i] = 0ull;
    if (gtid == 0) { g_candcnt = 0; g_cnt2 = 0; }
    gbar();

    // ---- P1: ordered score bits + level-1 histogram (item-major, coalesced) ----
    {
        float imH1 = __fsub_rn(img[0], 1.0f);
        float imW1 = __fsub_rn(img[1], 1.0f);
        float ms   = __fmul_rn(16.0f, img[2]);
        const float4* anc = (const float4*)anchors;
        for (int item = gtid; item < TOT; item += gs) {
            int a   = item >> 16;
            int pix = item & 65535;
            float score = probs[(NA + a) * HWPIX + pix];
            bool valid;
            (void)decode_box(pix, a, del, anc, imW1, imH1, ms, valid);
            u32 ob = 0u;
            if (valid) {
                u32 sb = __float_as_uint(score);
                ob = (sb & 0x80000000u) ? ~sb : (sb | 0x80000000u);
                atomicAdd(&g_hist[ob >> 16], 1u);
            }
            g_obs[item] = ob;
        }
    }
    gbar();

    // ---- P2: level-1 threshold (block 0) ----
    if (blockIdx.x == 0) {
        threshold_search(g_hist, PRE, &sh_bin, &sh_above);
        __syncthreads();
        if (tid == 0) { g_T1 = sh_bin; g_above = sh_above; }
    }
    gbar();

    // ---- P3: compact >= T1 + level-2 histogram ----
    {
        u32 T1 = (u32)g_T1;
        for (int v4 = gtid; v4 < TOT / 4; v4 += gs) {
            int base = v4 * 4;
            uint4 v = *(const uint4*)(g_obs + base);
            u32 obs4[4] = { v.x, v.y, v.z, v.w };
#pragma unroll
            for (int k = 0; k < 4; ++k) {
                u32 ob = obs4[k];
                bool keep = (ob != 0u) && ((ob >> 16) >= T1);
                u32 m = __ballot_sync(0xFFFFFFFFu, keep);
                if (keep) {
                    int rank = __popc(m & ((1u << lane) - 1));
                    int leader = __ffs(m) - 1;
                    int bp = 0;
                    if (lane == leader) bp = atomicAdd(&g_candcnt, __popc(m));
                    bp = __shfl_sync(m, bp, leader);
                    int idx2 = base + k;                      // item-major
                    int ti = (idx2 & 65535) * NA + (idx2 >> 16); // true rank index
                    int pos = bp + rank;
                    if (pos < CAPBIG)
                        g_cand[pos] = ((u64)ob << 32) | (u64)(0xFFFFFFFFu - (u32)ti);
                    if ((ob >> 16) == T1) atomicAdd(&g_hist2[ob & 0xFFFFu], 1u);
                }
            }
        }
    }
    gbar();

    // ---- P4: level-2 threshold (block 0) ----
    if (blockIdx.x == 0) {
        int need = PRE - (int)g_above;
        threshold_search(g_hist2, need, &sh_bin, &sh_above);
        __syncthreads();
        if (tid == 0)
            g_thr64 = ((u64)(u32)g_T1 << 48) | ((u64)(u32)sh_bin << 32);
    }
    gbar();

    // ---- P5: final filter into sort buffer ----
    {
        int cc = g_candcnt; if (cc > CAPBIG) cc = CAPBIG;
        u64 thr = g_thr64;
        for (int i = gtid; i < cc; i += gs) {
            u64 key = g_cand[i];
            if (key >= thr) {
                int pos = atomicAdd(&g_cnt2, 1);
                if (pos < SORTN) g_sortbuf[pos] = key;
            }
        }
    }
    gbar();

    // ---- P6: presort 4 chunks of 2048 (blocks 0-3, smem) ----
    if (blockIdx.x < 4) {
        int base = blockIdx.x * 2048;
        for (int t = tid; t < 2048; t += NTHR) sk[t] = g_sortbuf[base + t];
        __syncthreads();
        for (int k = 2; k <= 2048; k <<= 1) {
            for (int j = k >> 1; j > 0; j >>= 1) {
                for (int t = tid; t < 2048; t += NTHR) {
                    int l = t ^ j;
                    if (l > t) {
                        u64 a = sk[t], b = sk[l];
                        bool sw = (((base + t) & k) == 0) ? (a < b) : (a > b);
                        if (sw) { sk[t] = b; sk[l] = a; }
                    }
                }
                __syncthreads();
            }
        }
        for (int t = tid; t < 2048; t += NTHR) g_sortbuf[base + t] = sk[t];
    }
    gbar();

    // ---- P7: k=4096 merge entirely in smem (blocks 0-1, 4096 each) ----
    if (blockIdx.x < 2) {
        int base = blockIdx.x * 4096;
        for (int t = tid; t < 4096; t += NTHR) sk[t] = g_sortbuf[base + t];
        __syncthreads();
        for (int j = 2048; j > 0; j >>= 1) {
            for (int t = tid; t < 4096; t += NTHR) {
                int l = t ^ j;
                if (l > t) {
                    u64 a = sk[t], b = sk[l];
                    bool sw = (((base + t) & 4096) == 0) ? (a < b) : (a > b);
                    if (sw) { sk[t] = b; sk[l] = a; }
                }
            }
            __syncthreads();
        }
        for (int t = tid; t < 4096; t += NTHR) g_sortbuf[base + t] = sk[t];
    }
    gbar();

    // ---- P8: k=8192 final merge in smem (block 0, 64KB) ----
    if (blockIdx.x == 0) {
        for (int t = tid; t < 8192; t += NTHR) sk[t] = g_sortbuf[t];
        __syncthreads();
        for (int j = 4096; j > 0; j >>= 1) {
            for (int t = tid; t < 8192; t += NTHR) {
                int l = t ^ j;
                if (l > t) {
                    u64 a = sk[t], b = sk[l];
                    if (a < b) { sk[t] = b; sk[l] = a; }   // pure descending
                }
            }
            __syncthreads();
        }
        for (int t = tid; t < 8192; t += NTHR) g_sortbuf[t] = sk[t];
    }
    gbar();

    // ---- P9: decode top-6000 boxes + areas ----
    {
        float imH1 = __fsub_rn(img[0], 1.0f);
        float imW1 = __fsub_rn(img[1], 1.0f);
        float ms   = __fmul_rn(16.0f, img[2]);
        const float4* anc = (const float4*)anchors;
        for (int t = gtid; t < PRE; t += gs) {
            u64 key = g_sortbuf[t];
            float4 bx;
            if (key == 0ull) {
                atomicOr(&g_supp[t >> 6], 1ull << (t & 63));
                bx = make_float4(0.f, 0.f, 0.f, 0.f);
            } else {
                u32 idx = 0xFFFFFFFFu - (u32)(key & 0xFFFFFFFFull);
                int pix = idx / NA;
                int a   = idx - pix * NA;
                bool valid;
                bx = decode_box(pix, a, del, anc, imW1, imH1, ms, valid);
            }
            g_boxes[t] = bx;
            g_area[t] = __fmul_rn(__fadd_rn(__fsub_rn(bx.z, bx.x), 1.0f),
                                  __fadd_rn(__fsub_rn(bx.w, bx.y), 1.0f));
        }
    }
    gbar();

    // ---- P10: IoU bitmask (tiles of 64 cols x 1024 rows, striped over blocks) ----
    for (int tile = blockIdx.x; tile < NWORDS * 6; tile += nb) {
        int cB = tile % NWORDS;
        int rb = tile / NWORDS;
        int j0 = cB * 64;
        __syncthreads();
        if (tid < 64) {
            int j = j0 + tid;
            if (j < PRE) { cb[tid] = g_boxes[j]; ca[tid] = g_area[j]; }
            else         { cb[tid] = make_float4(0.f, 0.f, -1.f, -1.f); ca[tid] = 0.f; }
        }
        __syncthreads();
        int i = rb * NTHR + tid;
        if (i < PRE) {
            u64 word = 0ull;
            int c0 = (i >= j0) ? (i - j0 + 1) : 0;
            int cmax = min(64, PRE - j0);
            if (c0 < cmax) {
                float4 bi = g_boxes[i];
                float ai = g_area[i];
                for (int c = c0; c < cmax; ++c) {
                    float4 bj = cb[c];
                    float ix1 = fmaxf(bi.x, bj.x);
                    float iy1 = fmaxf(bi.y, bj.y);
                    float ix2 = fminf(bi.z, bj.z);
                    float iy2 = fminf(bi.w, bj.w);
                    float iw = fmaxf(__fadd_rn(__fsub_rn(ix2, ix1), 1.0f), 0.0f);
                    float ih = fmaxf(__fadd_rn(__fsub_rn(iy2, iy1), 1.0f), 0.0f);
                    float inter = __fmul_rn(iw, ih);
                    float u = __fsub_rn(__fadd_rn(ai, ca[c]), inter);
                    // exact predicate (iou > 0.7) with div only in borderline band
                    float t7  = __fmul_rn(NMS_T, u);
                    float d   = __fsub_rn(inter, t7);
                    float mar = __fmul_rn(2e-6f, u);
                    bool sup;
                    if (fabsf(d) <= mar) sup = (__fdiv_rn(inter, u) > NMS_T);
                    else                 sup = (d > 0.0f);
                    if (sup) word |= (1ull << c);
                }
            }
            g_mask[(size_t)i * WPITCH + cB] = word;
        }
    }
    gbar();

    // ---- P11: sequential NMS scan (block 0, warp 0) ----
    if (blockIdx.x != 0) return;
    if (tid < 32) {
        u64 S0 = g_supp[lane];
        u64 S1 = g_supp[lane + 32];
        u64 S2 = (lane < 30) ? g_supp[lane + 64] : 0ull;

        int kept = 0;
        for (int wi = 0; wi < NWORDS && kept < POST; ++wi) {
            int r_lo = wi * 64 + lane;
            int r_hi = r_lo + 32;
            u64 d_lo = g_mask[(size_t)r_lo * WPITCH + wi];
            u64 d_hi = (r_hi < PRE) ? g_mask[(size_t)r_hi * WPITCH + wi] : 0ull;

            int slot = wi >> 5, src = wi & 31;
            u64 mine = (slot == 0) ? S0 : ((slot == 1) ? S1 : S2);
            u64 w = __shfl_sync(0xFFFFFFFFu, mine, src);
            u64 alive = ~w;
            int bmax = min(64, PRE - wi * 64);
            if (bmax < 64) alive &= (1ull << bmax) - 1ull;

            while (alive && kept < POST) {
                int b = __ffsll(alive) - 1;
                alive &= alive - 1ull;
                int i = wi * 64 + b;

                const float* bp = (const float*)&g_boxes[i];
                if (lane < 4)       out[kept * 5 + 1 + lane] = bp[lane];
                else if (lane == 4) out[kept * 5] = 0.0f;
                kept++;

                size_t base = (size_t)i * WPITCH;
                S0 |= g_mask[base + lane];
                S1 |= g_mask[base + lane + 32];
                if (lane < 30) S2 |= g_mask[base + lane + 64];

                u64 dwb = __shfl_sync(0xFFFFFFFFu, (b < 32) ? d_lo : d_hi, b & 31);
                alive &= ~dwb;
            }
        }
        int rem = (POST - kept) * 5;
        for (int z = lane; z < rem; z += 32)
            out[kept * 5 + z] = 0.0f;
    }
}

// ---------------- launch: ONE persistent kernel ----------------
extern "C" void kernel_launch(void* const* d_in, const int* in_sizes, int n_in,
                              void* d_out, int out_size)
{
    const float* probs   = (const float*)d_in[0];
    const float* del     = (const float*)d_in[1];
    const float* img     = (const float*)d_in[2];
    const float* anchors = (const float*)d_in[3];
    float* out = (float*)d_out;

    cudaFuncSetAttribute(fused_proposal,
                         cudaFuncAttributeMaxDynamicSharedMemorySize, 65536);
    int dev = 0;
    cudaGetDevice(&dev);
    int nsm = 0;
    cudaDeviceGetAttribute(&nsm, cudaDevAttrMultiProcessorCount, dev);
    if (nsm < 8) nsm = 8;     // sort phases need >=4 blocks

    fused_proposal<<<nsm, NTHR, 65536>>>(probs, del, img, anchors, out);
}